// round 16
// baseline (speedup 1.0000x reference)
#include <cuda_runtime.h>
#include <cuda_bf16.h>
#include <cstdint>

// BinTokenizer: tokens = searchsorted(linspace(0,1,257), clip(x,1e-6,1-1e-6),
// 'right') - 1 == floor(clip(x)*256) (exact in fp32). Output dtype is FLOAT32
// (confirmed R9). Tokens 0..255 exact in fp32.
//
// R13: 2x float4/thread -> 157.3us, DRAM 85.8%, issue 14.8%.
// R14: 4x float4/thread (MLP_p1=4, half the waves, ~30% fewer instructions)
// to keep the DRAM queues dense across wave transitions. Streaming hints,
// 32-bit indexing, flat launch — all held from the R13 win.

#define N_BINS 256
#define EPS 1e-6f

__device__ __forceinline__ float tok1f(float x) {
    x = fminf(fmaxf(x, EPS), 1.0f - EPS);
    return floorf(x * 256.0f);        // in [0,255] by construction (clip)
}

__device__ __forceinline__ float4 tok4(float4 v) {
    float4 t;
    t.x = tok1f(v.x); t.y = tok1f(v.y);
    t.z = tok1f(v.z); t.w = tok1f(v.w);
    return t;
}

// Each block covers 1024 float4s: thread t handles base+t+{0,256,512,768}.
__global__ void __launch_bounds__(256)
bin_tokenizer_kernel(const float4* __restrict__ in, float4* __restrict__ out,
                     unsigned n4) {
    unsigned i0 = blockIdx.x * 1024u + threadIdx.x;
    if (i0 + 768u < n4) {             // steady state: all four in range
        float4 a = __ldcs(in + i0);
        float4 b = __ldcs(in + i0 + 256u);
        float4 c = __ldcs(in + i0 + 512u);
        float4 d = __ldcs(in + i0 + 768u);
        __stcs(out + i0,        tok4(a));
        __stcs(out + i0 + 256u, tok4(b));
        __stcs(out + i0 + 512u, tok4(c));
        __stcs(out + i0 + 768u, tok4(d));
    } else {
        #pragma unroll
        for (int k = 0; k < 4; k++) {
            unsigned i = i0 + (unsigned)k * 256u;
            if (i < n4) {
                float4 a = __ldcs(in + i);
                __stcs(out + i, tok4(a));
            }
        }
    }
}

__global__ void bin_tokenizer_tail(const float* __restrict__ in,
                                   float* __restrict__ out,
                                   long long start, long long n) {
    long long i = start + (long long)blockIdx.x * blockDim.x + threadIdx.x;
    if (i < n) out[i] = tok1f(in[i]);
}

extern "C" void kernel_launch(void* const* d_in, const int* in_sizes, int n_in,
                              void* d_out, int out_size) {
    // inputs = largest buffer; thresholds = smallest (units inference only).
    int xi = 0, ti = 0;
    for (int i = 1; i < n_in; i++) {
        if (in_sizes[i] > in_sizes[xi]) xi = i;
        if (in_sizes[i] < in_sizes[ti]) ti = i;
    }
    const long long nx_raw = (long long)in_sizes[xi];
    const long long nt_raw = (long long)in_sizes[ti];
    const long long os     = (long long)out_size;

    // Units detection (unchanged from the passing kernels).
    int scale;
    if      (nt_raw == (long long)(N_BINS + 1))      scale = 1;
    else if (nt_raw == 4LL * (N_BINS + 1))           scale = 4;
    else if (nx_raw == 4LL * os)                     scale = 4;
    else                                             scale = 1;

    long long n = nx_raw / scale;

    long long out_cap;
    if (os == n || os == 4LL * n) out_cap = n;
    else                          out_cap = (os < n) ? os : n;
    if (out_cap < n) n = out_cap;

    const float* in = (const float*)d_in[xi];
    float* out = (float*)d_out;
    long long n4 = n >> 2;

    if (n4 > 0) {
        unsigned blocks = (unsigned)((n4 + 1023) / 1024);  // 1024 float4s/block
        bin_tokenizer_kernel<<<blocks, 256>>>(
            (const float4*)in, (float4*)out, (unsigned)n4);
    }
    long long done = n4 << 2;
    if (done < n) {
        int rem = (int)(n - done);
        bin_tokenizer_tail<<<(rem + 255) / 256, 256>>>(in, out, done, n);
    }
}